// round 6
// baseline (speedup 1.0000x reference)
#include <cuda_runtime.h>

// Weighted BCE loss, mean-reduced, single fused kernel.
// loss_i = (t_i==1) ? -log(o_i + eps) : -8 * log(1 - o_i + eps);  out = mean(loss)

#define NEG_WEIGHT 8.0f
#define BCE_EPS    1e-7f

// Exactly one wave: 148 SMs x 8 resident blocks (256 thr, 31 regs -> 8 blocks/SM)
#define NBLOCKS  1184
#define NTHREADS 256

__device__ double       g_acc;    // zero-init; reset by last block each launch
__device__ unsigned int g_count;  // zero-init; reset by last block each launch

__device__ __forceinline__ float bce_elem(float o, int t) {
    // one log per element: x = t ? o : 1-o ; w = t ? 1 : 8
    float x = (t == 1) ? o : (1.0f - o);
    float w = (t == 1) ? 1.0f : NEG_WEIGHT;
    return w * (-__logf(x + BCE_EPS));
}

__device__ __forceinline__ float bce_quad(float4 o, int4 t) {
    // two independent chains to shorten FADD dependency
    float a = bce_elem(o.x, t.x) + bce_elem(o.z, t.z);
    float b = bce_elem(o.y, t.y) + bce_elem(o.w, t.w);
    return a + b;
}

__global__ void __launch_bounds__(NTHREADS)
bce_fused_kernel(const float4* __restrict__ out4,
                 const int4*   __restrict__ tgt4,
                 const float*  __restrict__ out_s,
                 const int*    __restrict__ tgt_s,
                 float* __restrict__ result,
                 int n4, int n)
{
    const int idx    = blockIdx.x * blockDim.x + threadIdx.x;
    const int stride = gridDim.x * blockDim.x;

    float acc0 = 0.0f, acc1 = 0.0f;

    // 2x unrolled grid-stride: front-batch 4 LDG.128 per iteration
    int i = idx;
    for (; i + stride < n4; i += 2 * stride) {
        float4 o0 = out4[i];
        int4   t0 = tgt4[i];
        float4 o1 = out4[i + stride];
        int4   t1 = tgt4[i + stride];
        acc0 += bce_quad(o0, t0);
        acc1 += bce_quad(o1, t1);
    }
    if (i < n4) {
        float4 o0 = out4[i];
        int4   t0 = tgt4[i];
        acc0 += bce_quad(o0, t0);
    }

    float acc = acc0 + acc1;

    // scalar tail (n not divisible by 4)
    if (idx == 0) {
        for (int k = n4 * 4; k < n; k++)
            acc += bce_elem(out_s[k], tgt_s[k]);
    }

    // intra-block reduction: warp shuffle, then smem across warps
    #pragma unroll
    for (int off = 16; off > 0; off >>= 1)
        acc += __shfl_down_sync(0xffffffffu, acc, off);

    __shared__ float s_warp[NTHREADS / 32];
    if ((threadIdx.x & 31) == 0)
        s_warp[threadIdx.x >> 5] = acc;
    __syncthreads();

    if (threadIdx.x == 0) {
        float bsum = 0.0f;
        #pragma unroll
        for (int w = 0; w < NTHREADS / 32; w++)
            bsum += s_warp[w];

        // cross-block accumulation in double, last block finalizes
        atomicAdd(&g_acc, (double)bsum);
        __threadfence();
        unsigned int old = atomicAdd(&g_count, 1u);
        if (old == gridDim.x - 1) {
            double total = g_acc;
            result[0] = (float)(total / (double)n);
            // reset for next graph replay
            g_acc   = 0.0;
            g_count = 0u;
            __threadfence();
        }
    }
}

extern "C" void kernel_launch(void* const* d_in, const int* in_sizes, int n_in,
                              void* d_out, int out_size)
{
    const float* outputs = (const float*)d_in[0];
    const int*   targets = (const int*)d_in[1];
    float* out = (float*)d_out;

    int n  = in_sizes[0];
    int n4 = n >> 2;

    bce_fused_kernel<<<NBLOCKS, NTHREADS>>>(
        (const float4*)outputs, (const int4*)targets,
        outputs, targets, out, n4, n);
}

// round 9
// speedup vs baseline: 1.0529x; 1.0529x over previous
#include <cuda_runtime.h>

// Weighted BCE loss, mean-reduced, single fused kernel with dynamic chunk stealing.
// loss_i = (t_i==1) ? -log(o_i + eps) : -8 * log(1 - o_i + eps);  out = mean(loss)

#define NEG_WEIGHT 8.0f
#define BCE_EPS    1e-7f

// Exactly one wave: 148 SMs x 8 resident blocks (256 thr, <=32 regs)
#define NBLOCKS   1184
#define NTHREADS  256
#define CHUNK_F4  512   // float4 elements per chunk (2 per thread)

__device__ double       g_acc;    // zero-init; reset by last block each launch
__device__ unsigned int g_count;  // zero-init; reset by last block each launch
__device__ unsigned int g_work;   // zero-init; reset by last block each launch

__device__ __forceinline__ float bce_elem(float o, int t) {
    // one log per element: x = t ? o : 1-o ; w = t ? 1 : 8
    float x = (t == 1) ? o : (1.0f - o);
    float w = (t == 1) ? 1.0f : NEG_WEIGHT;
    return w * (-__logf(x + BCE_EPS));
}

__device__ __forceinline__ float bce_quad(float4 o, int4 t) {
    float a = bce_elem(o.x, t.x) + bce_elem(o.z, t.z);
    float b = bce_elem(o.y, t.y) + bce_elem(o.w, t.w);
    return a + b;
}

__global__ void __launch_bounds__(NTHREADS)
bce_fused_kernel(const float4* __restrict__ out4,
                 const int4*   __restrict__ tgt4,
                 const float*  __restrict__ out_s,
                 const int*    __restrict__ tgt_s,
                 float* __restrict__ result,
                 int n4, int n, int nchunks)
{
    __shared__ int s_chunk;
    const int tid = threadIdx.x;

    float acc0 = 0.0f, acc1 = 0.0f;

    // first chunk is static (no startup atomic burst); later chunks stolen.
    int my = blockIdx.x;

    while (my < nchunks) {
        // prefetch the next chunk id while this one is processed
        __syncthreads();   // all threads have consumed s_chunk (no-op first iter)
        if (tid == 0)
            s_chunk = (int)(gridDim.x + atomicAdd(&g_work, 1u));

        int base = my * CHUNK_F4;
        int i0 = base + tid;
        int i1 = base + NTHREADS + tid;

        if (base + CHUNK_F4 <= n4) {
            // full chunk: 4 front-batched LDG.128
            float4 o0 = out4[i0];
            int4   t0 = tgt4[i0];
            float4 o1 = out4[i1];
            int4   t1 = tgt4[i1];
            acc0 += bce_quad(o0, t0);
            acc1 += bce_quad(o1, t1);
        } else {
            // guarded partial chunk
            if (i0 < n4) acc0 += bce_quad(out4[i0], tgt4[i0]);
            if (i1 < n4) acc1 += bce_quad(out4[i1], tgt4[i1]);
        }

        __syncthreads();
        my = s_chunk;
    }

    float acc = acc0 + acc1;

    // scalar tail (n not divisible by 4) — thread 0 of block 0
    if (blockIdx.x == 0 && tid == 0) {
        for (int k = n4 * 4; k < n; k++)
            acc += bce_elem(out_s[k], tgt_s[k]);
    }

    // intra-block reduction: warp shuffle, then smem across warps
    #pragma unroll
    for (int off = 16; off > 0; off >>= 1)
        acc += __shfl_down_sync(0xffffffffu, acc, off);

    __shared__ float s_warp[NTHREADS / 32];
    if ((tid & 31) == 0)
        s_warp[tid >> 5] = acc;
    __syncthreads();

    if (tid == 0) {
        float bsum = 0.0f;
        #pragma unroll
        for (int w = 0; w < NTHREADS / 32; w++)
            bsum += s_warp[w];

        // cross-block accumulation in double, last block finalizes
        atomicAdd(&g_acc, (double)bsum);
        __threadfence();
        unsigned int old = atomicAdd(&g_count, 1u);
        if (old == gridDim.x - 1) {
            double total = g_acc;
            result[0] = (float)(total / (double)n);
            // reset for next graph replay
            g_acc   = 0.0;
            g_count = 0u;
            g_work  = 0u;
            __threadfence();
        }
    }
}

extern "C" void kernel_launch(void* const* d_in, const int* in_sizes, int n_in,
                              void* d_out, int out_size)
{
    const float* outputs = (const float*)d_in[0];
    const int*   targets = (const int*)d_in[1];
    float* out = (float*)d_out;

    int n  = in_sizes[0];
    int n4 = n >> 2;
    int nchunks = (n4 + CHUNK_F4 - 1) / CHUNK_F4;

    bce_fused_kernel<<<NBLOCKS, NTHREADS>>>(
        (const float4*)outputs, (const int4*)targets,
        outputs, targets, out, n4, n, nchunks);
}